// round 8
// baseline (speedup 1.0000x reference)
#include <cuda_runtime.h>
#include <math_constants.h>

// EvalEig: eigenvalues of 16 symmetric tridiagonal matrices (B=4, L=4, N=2000)
// Two-phase cooperative Sturm method, 512-thread blocks (4 warps/SMSP):
//   Phase 1: 1024-point split grid (2 packed probes/thread, ONE sweep);
//     448*2=896 fine points over the bulk band [b0, b0+4.85], 128 coarse.
//   Phase 2: ONE pentasection round -- threads t and t+256 pair up on the
//     same eigenvalue, evaluating probes {1,2} and {3,4} of lo+i*w/5;
//     counts merged through shared -> interval/5 in a single sweep.
// Recurrence (scaled, offdiag=1): q_i = fma(sigma_i*(a_i-x), q_{i-1}, q_{i-2}),
// sigma_i=-1 odd i; sigma_i*a_i pre-packed u64 {sa,sa} in shared. Signs per 32
// steps via popc; exponent-hack rescale (s=2^-ilogb(qc)) every 16 steps.
// Tiles ping-pong prefetched into registers.

#define RN       2000
#define NMAT     16
#define NTHREADS 512
#define BLKS_PER_MAT 8        // 8 * 256 eigenvalues = 2048 >= 2000
#define INV_B    0.0025f      // 1/400
#define BSCALE   400.0f
#define NGRID    1024
#define NFINE    896
#define FINE_W   4.85f

typedef unsigned long long u64;

__device__ __forceinline__ u64 pack2(float x, float y) {
    u64 r; asm("mov.b64 %0, {%1, %2};" : "=l"(r) : "f"(x), "f"(y)); return r;
}
__device__ __forceinline__ u64 add2(u64 a, u64 b) {
    u64 d; asm("add.rn.f32x2 %0, %1, %2;" : "=l"(d) : "l"(a), "l"(b)); return d;
}
__device__ __forceinline__ u64 fma2(u64 a, u64 b, u64 c) {
    u64 d; asm("fma.rn.f32x2 %0, %1, %2, %3;" : "=l"(d) : "l"(a), "l"(b), "l"(c)); return d;
}
__device__ __forceinline__ unsigned lo32(u64 x) { return (unsigned)x; }
__device__ __forceinline__ unsigned hi32(u64 x) { return (unsigned)(x >> 32); }

struct Tile { ulonglong2 v[8]; };   // 16 steps of {sa,sa}

__device__ __forceinline__ void load_tile(Tile& t, const ulonglong2* __restrict__ p) {
#pragma unroll
    for (int j = 0; j < 8; j++) t.v[j] = p[j];
}

// 16 recurrence steps from a register tile, then exponent-hack rescale.
__device__ __forceinline__ void do16(const Tile& t, u64 pxh, u64 nxh,
                                     u64& qc, u64& qp,
                                     unsigned& mlo, unsigned& mhi) {
#pragma unroll
    for (int j = 0; j < 8; j++) {
        u64 qn = fma2(add2(t.v[j].x, pxh), qc, qp);
        qp = qc; qc = qn;
        mlo = __funnelshift_l(lo32(qc), mlo, 1);
        mhi = __funnelshift_l(hi32(qc), mhi, 1);
        qn = fma2(add2(t.v[j].y, nxh), qc, qp);
        qp = qc; qc = qn;
        mlo = __funnelshift_l(lo32(qc), mlo, 1);
        mhi = __funnelshift_l(hi32(qc), mhi, 1);
    }
    unsigned eb0 = lo32(qc) & 0x7F800000u;
    unsigned eb1 = hi32(qc) & 0x7F800000u;
    float s0 = __uint_as_float(0x7F000000u - eb0);   // 2^(-ilogb), always > 0
    float s1 = __uint_as_float(0x7F000000u - eb1);
    qc = pack2(__uint_as_float(lo32(qc)) * s0, __uint_as_float(hi32(qc)) * s1);
    qp = pack2(__uint_as_float(lo32(qp)) * s0, __uint_as_float(hi32(qp)) * s1);
}

// Packed Sturm counts at {x1 (lo), x2 (hi)}; ping-pong prefetched tiles.
__device__ __forceinline__ void sturm2(const u64* __restrict__ sdp,
                                       float x1, float x2, int& c1, int& c2) {
    const u64 pxh = pack2( x1,  x2);
    const u64 nxh = pack2(-x1, -x2);
    const ulonglong2* __restrict__ p = reinterpret_cast<const ulonglong2*>(sdp);
    u64 qp = 0;
    u64 qc = pack2(1.0f, 1.0f);
    unsigned mlo = 0, mhi = 0;
    int clo = 0, chi = 0;

    Tile A, B;
    load_tile(A, p);
#pragma unroll 1
    for (int w = 0; w < 62; w++) {        // halves 2w, 2w+1; preload 2w+2
        const unsigned plo = mlo, phi = mhi;
        load_tile(B, p + (2 * w + 1) * 8);
        do16(A, pxh, nxh, qc, qp, mlo, mhi);
        load_tile(A, p + (2 * w + 2) * 8);
        do16(B, pxh, nxh, qc, qp, mlo, mhi);
        clo += __popc((mlo ^ ((mlo >> 1) | (plo << 31))) ^ 0xAAAAAAAAu);
        chi += __popc((mhi ^ ((mhi >> 1) | (phi << 31))) ^ 0xAAAAAAAAu);
    }
    do16(A, pxh, nxh, qc, qp, mlo, mhi);  // 16-step tail (steps 1985..2000)
    clo += __popc(((mlo ^ (mlo >> 1)) & 0xFFFFu) ^ 0xAAAAu);
    chi += __popc(((mhi ^ (mhi >> 1)) & 0xFFFFu) ^ 0xAAAAu);
    c1 = clo; c2 = chi;
}

__global__ __launch_bounds__(NTHREADS, 1)
void eval_eig_kernel(const float* __restrict__ ptl, float* __restrict__ out) {
    __shared__ __align__(16) u64 sdp[RN];      // {sigma_i*a_i, same} packed
    __shared__ int   ctab[NGRID + 1];
    __shared__ int2  scnt[NTHREADS];           // pentasection count exchange
    __shared__ float wmin[NTHREADS / 32], wmax[NTHREADS / 32];
    __shared__ float bounds[2];

    const int mat = blockIdx.y;                // 0..15 -> (b, l)
    const int b   = mat >> 2;
    const int l   = mat & 3;
    const float ll1 = (float)(l * (l + 1));
    const int t   = threadIdx.x;

    // Scaled, signed, duplicated diagonal; Gershgorin min/max of a.
    const float step = 99.95f / 1999.0f;       // jnp.linspace(0.05, 100, 2000)
    float lmin = CUDART_INF_F, lmax = -CUDART_INF_F;
    for (int i = t; i < RN; i += NTHREADS) {
        float r  = 0.05f + step * (float)i;
        float a  = (800.0f + ptl[b * RN + i] + ll1 / (r * r)) * INV_B;
        float sa = (i & 1) ? a : -a;
        sdp[i] = pack2(sa, sa);
        lmin = fminf(lmin, a);
        lmax = fmaxf(lmax, a);
    }
#pragma unroll
    for (int off = 16; off; off >>= 1) {
        lmin = fminf(lmin, __shfl_xor_sync(0xffffffffu, lmin, off));
        lmax = fmaxf(lmax, __shfl_xor_sync(0xffffffffu, lmax, off));
    }
    const int wid = t >> 5;
    if ((t & 31) == 0) { wmin[wid] = lmin; wmax[wid] = lmax; }
    __syncthreads();
    if (t == 0) {
        float a = wmin[0], c = wmax[0];
#pragma unroll
        for (int w = 1; w < NTHREADS / 32; w++) {
            a = fminf(a, wmin[w]);
            c = fmaxf(c, wmax[w]);
        }
        bounds[0] = a - 2.001f;    // scaled offdiag row sum = 2
        bounds[1] = c + 2.001f;
    }
    __syncthreads();

    const float b0 = bounds[0];
    const float b1 = bounds[1];
    const float cs = fminf(b0 + FINE_W, b1);             // fine/coarse split
    const float gwf = (cs - b0) * (1.0f / (float)NFINE);
    const float gwc = (b1 - cs) * (1.0f / (float)(NGRID - NFINE));

    auto gridx = [&](int j) -> float {
        return (j <= NFINE) ? b0 + gwf * (float)j
                            : cs + gwc * (float)(j - NFINE);
    };

    // ---- Phase 1: 1024-point split grid (2 probes/thread, ONE sweep) ----
    {
        int c1, c2;
        sturm2(sdp, gridx(2 * t + 1), gridx(2 * t + 2), c1, c2);
        ctab[2 * t + 1] = c1;
        ctab[2 * t + 2] = c2;
    }
    __syncthreads();
    if (t == 0) { ctab[0] = 0; ctab[NGRID] = RN; }
    __syncthreads();
    {   // one monotone relaxation pass (ulp-flip insurance)
        int v1 = max(ctab[t], ctab[t + 1]);
        int v2 = max(ctab[t + NTHREADS], ctab[t + NTHREADS + 1]);
        __syncthreads();
        ctab[t + 1] = v1;
        ctab[t + NTHREADS + 1] = v2;
    }
    __syncthreads();

    // ---- Phase 2: ONE pentasection round, thread pairs share an eigenvalue ----
    const int tk   = t & 255;
    const int half = t >> 8;                    // 0 -> probes {1,2}, 1 -> {3,4}
    const int k    = blockIdx.x * 256 + tk;
    const int kk   = min(k, RN - 1);

    int jlo = 0, jhi = NGRID;      // invariant: ctab[jlo] <= kk < ctab[jhi]
#pragma unroll
    for (int s = 0; s < 10; s++) {
        int jm = (jlo + jhi) >> 1;
        if (ctab[jm] <= kk) jlo = jm; else jhi = jm;
    }
    const float lo = gridx(jlo);
    const float hi = gridx(jhi);
    const float w5 = (hi - lo) * 0.2f;

    {
        float xA = lo + w5 * (float)(1 + 2 * half);
        float xB = lo + w5 * (float)(2 + 2 * half);
        int cA, cB;
        sturm2(sdp, xA, xB, cA, cB);
        scnt[t] = make_int2(cA, cB);
    }
    __syncthreads();

    if (half == 0 && k < RN) {
        int2 p12 = scnt[t];            // counts at lo+w5, lo+2w5
        int2 p34 = scnt[t + 256];      // counts at lo+3w5, lo+4w5
        float nlo, nhi;
        if      (p12.x > kk) { nlo = lo;            nhi = lo + w5;        }
        else if (p12.y > kk) { nlo = lo + w5;       nhi = lo + 2.0f * w5; }
        else if (p34.x > kk) { nlo = lo + 2.0f * w5; nhi = lo + 3.0f * w5; }
        else if (p34.y > kk) { nlo = lo + 3.0f * w5; nhi = lo + 4.0f * w5; }
        else                 { nlo = lo + 4.0f * w5; nhi = hi;            }
        out[mat * RN + k] = BSCALE * (0.5f * (nlo + nhi));
    }
}

extern "C" void kernel_launch(void* const* d_in, const int* in_sizes, int n_in,
                              void* d_out, int out_size) {
    (void)in_sizes; (void)n_in; (void)out_size;
    const float* ptl = (const float*)d_in[0];
    float* out = (float*)d_out;
    dim3 grid(BLKS_PER_MAT, NMAT);   // (8, 16) = 128 blocks, 512 threads
    eval_eig_kernel<<<grid, NTHREADS>>>(ptl, out);
}

// round 9
// speedup vs baseline: 1.9326x; 1.9326x over previous
#include <cuda_runtime.h>
#include <math_constants.h>

// EvalEig: eigenvalues of 16 symmetric tridiagonal matrices (B=4, L=4, N=2000)
// SINGLE-SWEEP Sturm method. 9 blocks per matrix; each block evaluates 512
// consecutive probes of a 4600-point split grid (2 packed probes/thread,
// ONE sweep). Blocks overlap by one probe (stride 511) so every adjacent
// probe pair is owned by exactly one block; each block then emits every
// eigenvalue bracketed by one of its pairs as the bracket midpoint.
// Grid: 4000 fine points over the bulk band [b0, b0+4.85] (bracket 0.49 real,
// = R7's final width) + 600 coarse points above (isolated barrier states).
// Recurrence (scaled, offdiag=1): q_i = fma(sigma_i*(a_i-x), q_{i-1}, q_{i-2}),
// sigma_i=-1 odd i; sigma_i*a_i pre-packed u64 {sa,sa} in shared. Signs per 32
// steps via popc; exponent-hack rescale (s=2^-ilogb(qc)) every 16 steps.
// Tiles ping-pong prefetched into registers.

#define RN       2000
#define NMAT     16
#define NTHREADS 256
#define BLKS_PER_MAT 9
#define PROBE_STRIDE 511      // block j owns global probes [511j, 511j+511]
#define NGRID    4600         // last probe index = 8*511+511 = 4599
#define NFINE    4000
#define FINE_W   4.85f
#define INV_B    0.0025f      // 1/400
#define BSCALE   400.0f

typedef unsigned long long u64;

__device__ __forceinline__ u64 pack2(float x, float y) {
    u64 r; asm("mov.b64 %0, {%1, %2};" : "=l"(r) : "f"(x), "f"(y)); return r;
}
__device__ __forceinline__ u64 add2(u64 a, u64 b) {
    u64 d; asm("add.rn.f32x2 %0, %1, %2;" : "=l"(d) : "l"(a), "l"(b)); return d;
}
__device__ __forceinline__ u64 fma2(u64 a, u64 b, u64 c) {
    u64 d; asm("fma.rn.f32x2 %0, %1, %2, %3;" : "=l"(d) : "l"(a), "l"(b), "l"(c)); return d;
}
__device__ __forceinline__ unsigned lo32(u64 x) { return (unsigned)x; }
__device__ __forceinline__ unsigned hi32(u64 x) { return (unsigned)(x >> 32); }

struct Tile { ulonglong2 v[8]; };   // 16 steps of {sa,sa}

__device__ __forceinline__ void load_tile(Tile& t, const ulonglong2* __restrict__ p) {
#pragma unroll
    for (int j = 0; j < 8; j++) t.v[j] = p[j];
}

// 16 recurrence steps from a register tile, then exponent-hack rescale.
__device__ __forceinline__ void do16(const Tile& t, u64 pxh, u64 nxh,
                                     u64& qc, u64& qp,
                                     unsigned& mlo, unsigned& mhi) {
#pragma unroll
    for (int j = 0; j < 8; j++) {
        u64 qn = fma2(add2(t.v[j].x, pxh), qc, qp);
        qp = qc; qc = qn;
        mlo = __funnelshift_l(lo32(qc), mlo, 1);
        mhi = __funnelshift_l(hi32(qc), mhi, 1);
        qn = fma2(add2(t.v[j].y, nxh), qc, qp);
        qp = qc; qc = qn;
        mlo = __funnelshift_l(lo32(qc), mlo, 1);
        mhi = __funnelshift_l(hi32(qc), mhi, 1);
    }
    unsigned eb0 = lo32(qc) & 0x7F800000u;
    unsigned eb1 = hi32(qc) & 0x7F800000u;
    float s0 = __uint_as_float(0x7F000000u - eb0);   // 2^(-ilogb), always > 0
    float s1 = __uint_as_float(0x7F000000u - eb1);
    qc = pack2(__uint_as_float(lo32(qc)) * s0, __uint_as_float(hi32(qc)) * s1);
    qp = pack2(__uint_as_float(lo32(qp)) * s0, __uint_as_float(hi32(qp)) * s1);
}

// Packed Sturm counts at {x1 (lo), x2 (hi)}; ping-pong prefetched tiles.
__device__ __forceinline__ void sturm2(const u64* __restrict__ sdp,
                                       float x1, float x2, int& c1, int& c2) {
    const u64 pxh = pack2( x1,  x2);
    const u64 nxh = pack2(-x1, -x2);
    const ulonglong2* __restrict__ p = reinterpret_cast<const ulonglong2*>(sdp);
    u64 qp = 0;
    u64 qc = pack2(1.0f, 1.0f);
    unsigned mlo = 0, mhi = 0;
    int clo = 0, chi = 0;

    Tile A, B;
    load_tile(A, p);
#pragma unroll 1
    for (int w = 0; w < 62; w++) {        // halves 2w, 2w+1; preload 2w+2
        const unsigned plo = mlo, phi = mhi;
        load_tile(B, p + (2 * w + 1) * 8);
        do16(A, pxh, nxh, qc, qp, mlo, mhi);
        load_tile(A, p + (2 * w + 2) * 8);
        do16(B, pxh, nxh, qc, qp, mlo, mhi);
        clo += __popc((mlo ^ ((mlo >> 1) | (plo << 31))) ^ 0xAAAAAAAAu);
        chi += __popc((mhi ^ ((mhi >> 1) | (phi << 31))) ^ 0xAAAAAAAAu);
    }
    do16(A, pxh, nxh, qc, qp, mlo, mhi);  // 16-step tail (steps 1985..2000)
    clo += __popc(((mlo ^ (mlo >> 1)) & 0xFFFFu) ^ 0xAAAAu);
    chi += __popc(((mhi ^ (mhi >> 1)) & 0xFFFFu) ^ 0xAAAAu);
    c1 = clo; c2 = chi;
}

__global__ __launch_bounds__(NTHREADS, 1)
void eval_eig_kernel(const float* __restrict__ ptl, float* __restrict__ out) {
    __shared__ __align__(16) u64 sdp[RN];      // {sigma_i*a_i, same} packed
    __shared__ int   sc[512];                  // counts at this block's probes
    __shared__ float wmin[NTHREADS / 32], wmax[NTHREADS / 32];
    __shared__ float bounds[2];

    const int mat = blockIdx.y;                // 0..15 -> (b, l)
    const int b   = mat >> 2;
    const int l   = mat & 3;
    const float ll1 = (float)(l * (l + 1));
    const int t   = threadIdx.x;

    // Scaled, signed, duplicated diagonal; Gershgorin min/max of a.
    // Identical code/data in every block of this matrix -> bitwise-identical
    // bounds and probe positions across blocks (needed at slice boundaries).
    const float step = 99.95f / 1999.0f;       // jnp.linspace(0.05, 100, 2000)
    float lmin = CUDART_INF_F, lmax = -CUDART_INF_F;
    for (int i = t; i < RN; i += NTHREADS) {
        float r  = 0.05f + step * (float)i;
        float a  = (800.0f + ptl[b * RN + i] + ll1 / (r * r)) * INV_B;
        float sa = (i & 1) ? a : -a;
        sdp[i] = pack2(sa, sa);
        lmin = fminf(lmin, a);
        lmax = fmaxf(lmax, a);
    }
#pragma unroll
    for (int off = 16; off; off >>= 1) {
        lmin = fminf(lmin, __shfl_xor_sync(0xffffffffu, lmin, off));
        lmax = fmaxf(lmax, __shfl_xor_sync(0xffffffffu, lmax, off));
    }
    const int wid = t >> 5;
    if ((t & 31) == 0) { wmin[wid] = lmin; wmax[wid] = lmax; }
    __syncthreads();
    if (t == 0) {
        float a = wmin[0], c = wmax[0];
#pragma unroll
        for (int w = 1; w < NTHREADS / 32; w++) {
            a = fminf(a, wmin[w]);
            c = fmaxf(c, wmax[w]);
        }
        bounds[0] = a - 2.001f;    // scaled offdiag row sum = 2; count(b0)=0
        bounds[1] = c + 2.001f;    // count(b1)=RN
    }
    __syncthreads();

    const float b0 = bounds[0];
    const float b1 = bounds[1];
    const float cs = fminf(b0 + FINE_W, b1);   // fine/coarse split (may = b1)
    const float gwf = (cs - b0) * (1.0f / (float)NFINE);
    const float gwc = (b1 - cs) * (1.0f / (float)(NGRID - 1 - NFINE));

    // x(g) on the split grid; x(0)=b0, x(NGRID-1)=b1.
    auto gridx = [&](int g) -> float {
        return (g <= NFINE) ? b0 + gwf * (float)g
                            : cs + gwc * (float)(g - NFINE);
    };

    // ---- The ONE sweep: this block's 512 probes (2 per thread, packed) ----
    const int g0 = blockIdx.x * PROBE_STRIDE;  // first global probe index
    {
        int c1, c2;
        sturm2(sdp, gridx(g0 + 2 * t), gridx(g0 + 2 * t + 1), c1, c2);
        sc[2 * t]     = c1;
        sc[2 * t + 1] = c2;
    }
    __syncthreads();

    // ---- Emit: each adjacent pair (u, u+1), u = 0..510, brackets the
    // eigenvalues k in [sc[u], sc[u+1]) at midpoint. Integer-walk coverage
    // guarantees every k in [0, RN) is written by some block (count(b0)=0,
    // count(b1)=RN; duplicate boundary probes are bitwise-identical).
#pragma unroll
    for (int h = 0; h < 2; h++) {
        int u = 2 * t + h;
        if (u < 511) {
            int cL = sc[u], cR = sc[u + 1];
            if (cR > cL) {
                float xm = 0.5f * (gridx(g0 + u) + gridx(g0 + u + 1)) * BSCALE;
                for (int k = cL; k < cR; k++) out[mat * RN + k] = xm;
            }
        }
    }
}

extern "C" void kernel_launch(void* const* d_in, const int* in_sizes, int n_in,
                              void* d_out, int out_size) {
    (void)in_sizes; (void)n_in; (void)out_size;
    const float* ptl = (const float*)d_in[0];
    float* out = (float*)d_out;
    dim3 grid(BLKS_PER_MAT, NMAT);   // (9, 16) = 144 blocks, 256 threads
    eval_eig_kernel<<<grid, NTHREADS>>>(ptl, out);
}

// round 11
// speedup vs baseline: 3.5913x; 1.8582x over previous
#include <cuda_runtime.h>
#include <math_constants.h>

// EvalEig: eigenvalues of 16 symmetric tridiagonal matrices (B=4, L=4, N=2000)
// SINGLE-SWEEP Sturm: 9 blocks/matrix x 128 threads (1 warp/SMSP), each block
// evaluates 256 consecutive probes of a 2296-point split grid (2 packed
// probes/thread, ONE sweep), then emits every eigenvalue bracketed by one of
// its adjacent probe pairs at the bracket midpoint.
// Recurrence (scaled, offdiag=1): q_i = fma(sigma_i*(a_i-x), q_{i-1}, q_{i-2}),
// sigma=-1 on odd steps (sign substitution q = eps*p, eps = +,-,-,+ period 4).
// Sign bits go into TWO alternating masks (mA: odd/A steps, mB: even/B steps)
// so each funnel-shift chain updates every 2 steps (breaks the 8 cyc/step SHF
// dependency that bound R9). p-sign-change counting per 32-step window
// (eps parity: pairs ENDING AT ODD (A) STEPS flip, pairs ending at B do not):
//   popc( (mA ^ mB)            & 0xFFFF)   A->B pairs (end even, no flip)
// + popc(~(mB ^ (mA << 1))     & 0xFFFE)   B->A pairs (end odd, flip)
// + (~(pB ^ (mA >> 15))        & 1)        boundary pair (ends odd, flip)

#define RN       2000
#define NMAT     16
#define NTHREADS 128
#define BLKS_PER_MAT 9
#define PROBE_STRIDE 255      // block j owns global probes [255j, 255j+255]
#define NGRID    2296         // last probe = 8*255+255 = 2295
#define NFINE    2000
#define FINE_W   4.85f
#define INV_B    0.0025f      // 1/400
#define BSCALE   400.0f

typedef unsigned long long u64;

__device__ __forceinline__ u64 pack2(float x, float y) {
    u64 r; asm("mov.b64 %0, {%1, %2};" : "=l"(r) : "f"(x), "f"(y)); return r;
}
__device__ __forceinline__ u64 add2(u64 a, u64 b) {
    u64 d; asm("add.rn.f32x2 %0, %1, %2;" : "=l"(d) : "l"(a), "l"(b)); return d;
}
__device__ __forceinline__ u64 fma2(u64 a, u64 b, u64 c) {
    u64 d; asm("fma.rn.f32x2 %0, %1, %2, %3;" : "=l"(d) : "l"(a), "l"(b), "l"(c)); return d;
}
__device__ __forceinline__ unsigned lo32(u64 x) { return (unsigned)x; }
__device__ __forceinline__ unsigned hi32(u64 x) { return (unsigned)(x >> 32); }

struct Tile { ulonglong2 v[8]; };   // 16 steps of {sa,sa}

__device__ __forceinline__ void load_tile(Tile& t, const ulonglong2* __restrict__ p) {
#pragma unroll
    for (int j = 0; j < 8; j++) t.v[j] = p[j];
}

// 16 recurrence steps (8 A/B double-steps) + exponent-hack rescale.
__device__ __forceinline__ void do16(const Tile& t, u64 pxh, u64 nxh,
                                     u64& qc, u64& qp,
                                     unsigned& mAlo, unsigned& mAhi,
                                     unsigned& mBlo, unsigned& mBhi) {
#pragma unroll
    for (int j = 0; j < 8; j++) {
        u64 qn = fma2(add2(t.v[j].x, pxh), qc, qp);   // A (odd poly step)
        qp = qc; qc = qn;
        mAlo = __funnelshift_l(lo32(qc), mAlo, 1);
        mAhi = __funnelshift_l(hi32(qc), mAhi, 1);
        qn = fma2(add2(t.v[j].y, nxh), qc, qp);       // B (even poly step)
        qp = qc; qc = qn;
        mBlo = __funnelshift_l(lo32(qc), mBlo, 1);
        mBhi = __funnelshift_l(hi32(qc), mBhi, 1);
    }
    unsigned eb0 = lo32(qc) & 0x7F800000u;
    unsigned eb1 = hi32(qc) & 0x7F800000u;
    float s0 = __uint_as_float(0x7F000000u - eb0);    // 2^(-ilogb), > 0
    float s1 = __uint_as_float(0x7F000000u - eb1);
    qc = pack2(__uint_as_float(lo32(qc)) * s0, __uint_as_float(hi32(qc)) * s1);
    qp = pack2(__uint_as_float(lo32(qp)) * s0, __uint_as_float(hi32(qp)) * s1);
}

// Packed Sturm counts at {x1 (lo), x2 (hi)}; ping-pong prefetched tiles.
__device__ __forceinline__ void sturm2(const u64* __restrict__ sdp,
                                       float x1, float x2, int& c1, int& c2) {
    const u64 pxh = pack2( x1,  x2);
    const u64 nxh = pack2(-x1, -x2);
    const ulonglong2* __restrict__ p = reinterpret_cast<const ulonglong2*>(sdp);
    u64 qp = 0;
    u64 qc = pack2(1.0f, 1.0f);
    unsigned mAlo = 0, mAhi = 0, mBlo = 0, mBhi = 0;
    unsigned pBlo = 0, pBhi = 0;   // sign at last even step of prev window (q0=+)
    int clo = 0, chi = 0;

    Tile A, B;
    load_tile(A, p);
#pragma unroll 1
    for (int w = 0; w < 62; w++) {        // 32-step window; preload next tiles
        load_tile(B, p + (2 * w + 1) * 8);
        do16(A, pxh, nxh, qc, qp, mAlo, mAhi, mBlo, mBhi);
        load_tile(A, p + (2 * w + 2) * 8);
        do16(B, pxh, nxh, qc, qp, mAlo, mAhi, mBlo, mBhi);
        clo += __popc((mAlo ^ mBlo) & 0xFFFFu)                  // end-B: no flip
             + __popc((~(mBlo ^ (mAlo << 1))) & 0xFFFEu)        // end-A: flip
             + (int)((~(pBlo ^ (mAlo >> 15))) & 1u);            // boundary: flip
        chi += __popc((mAhi ^ mBhi) & 0xFFFFu)
             + __popc((~(mBhi ^ (mAhi << 1))) & 0xFFFEu)
             + (int)((~(pBhi ^ (mAhi >> 15))) & 1u);
        pBlo = mBlo & 1u;
        pBhi = mBhi & 1u;
    }
    // 16-step tail (8 A-bits, 8 B-bits).
    do16(A, pxh, nxh, qc, qp, mAlo, mAhi, mBlo, mBhi);
    clo += __popc((mAlo ^ mBlo) & 0xFFu)
         + __popc((~(mBlo ^ (mAlo << 1))) & 0xFEu)
         + (int)((~(pBlo ^ (mAlo >> 7))) & 1u);
    chi += __popc((mAhi ^ mBhi) & 0xFFu)
         + __popc((~(mBhi ^ (mAhi << 1))) & 0xFEu)
         + (int)((~(pBhi ^ (mAhi >> 7))) & 1u);
    c1 = clo; c2 = chi;
}

__global__ __launch_bounds__(NTHREADS, 1)
void eval_eig_kernel(const float* __restrict__ ptl, float* __restrict__ out) {
    __shared__ __align__(16) u64 sdp[RN];      // {sigma_i*a_i, same} packed
    __shared__ int   sc[2 * NTHREADS];         // counts at this block's probes
    __shared__ float wmin[NTHREADS / 32], wmax[NTHREADS / 32];
    __shared__ float bounds[2];

    const int mat = blockIdx.y;                // 0..15 -> (b, l)
    const int b   = mat >> 2;
    const int l   = mat & 3;
    const float ll1 = (float)(l * (l + 1));
    const int t   = threadIdx.x;

    // Scaled, signed, duplicated diagonal; Gershgorin min/max of a.
    // Bitwise-identical across the matrix's 9 blocks (boundary determinism).
    const float step = 99.95f / 1999.0f;       // jnp.linspace(0.05, 100, 2000)
    float lmin = CUDART_INF_F, lmax = -CUDART_INF_F;
    for (int i = t; i < RN; i += NTHREADS) {
        float r  = 0.05f + step * (float)i;
        float a  = (800.0f + ptl[b * RN + i] + ll1 / (r * r)) * INV_B;
        float sa = (i & 1) ? a : -a;
        sdp[i] = pack2(sa, sa);
        lmin = fminf(lmin, a);
        lmax = fmaxf(lmax, a);
    }
#pragma unroll
    for (int off = 16; off; off >>= 1) {
        lmin = fminf(lmin, __shfl_xor_sync(0xffffffffu, lmin, off));
        lmax = fmaxf(lmax, __shfl_xor_sync(0xffffffffu, lmax, off));
    }
    const int wid = t >> 5;
    if ((t & 31) == 0) { wmin[wid] = lmin; wmax[wid] = lmax; }
    __syncthreads();
    if (t == 0) {
        float a = wmin[0], c = wmax[0];
#pragma unroll
        for (int w = 1; w < NTHREADS / 32; w++) {
            a = fminf(a, wmin[w]);
            c = fmaxf(c, wmax[w]);
        }
        bounds[0] = a - 2.001f;    // count(b0)=0
        bounds[1] = c + 2.001f;    // count(b1)=RN
    }
    __syncthreads();

    const float b0 = bounds[0];
    const float b1 = bounds[1];
    const float cs = fminf(b0 + FINE_W, b1);
    const float gwf = (cs - b0) * (1.0f / (float)NFINE);
    const float gwc = (b1 - cs) * (1.0f / (float)(NGRID - 1 - NFINE));

    auto gridx = [&](int g) -> float {
        return (g <= NFINE) ? b0 + gwf * (float)g
                            : cs + gwc * (float)(g - NFINE);
    };

    // ---- The ONE sweep: this block's 256 probes (2 per thread, packed) ----
    const int g0 = blockIdx.x * PROBE_STRIDE;
    {
        int c1, c2;
        sturm2(sdp, gridx(g0 + 2 * t), gridx(g0 + 2 * t + 1), c1, c2);
        sc[2 * t]     = c1;
        sc[2 * t + 1] = c2;
    }
    __syncthreads();

    // ---- Emit: pair (u, u+1), u = 0..254, brackets eigenvalues
    // [sc[u], sc[u+1]) at midpoint. Integer-walk telescoping + duplicated
    // boundary probes (bitwise-identical across blocks) cover all k in [0,RN).
#pragma unroll
    for (int h = 0; h < 2; h++) {
        int u = 2 * t + h;
        if (u < 2 * NTHREADS - 1) {
            int cL = sc[u], cR = sc[u + 1];
            if (cR > cL) {
                float xm = 0.5f * (gridx(g0 + u) + gridx(g0 + u + 1)) * BSCALE;
                for (int k = cL; k < cR; k++) out[mat * RN + k] = xm;
            }
        }
    }
}

extern "C" void kernel_launch(void* const* d_in, const int* in_sizes, int n_in,
                              void* d_out, int out_size) {
    (void)in_sizes; (void)n_in; (void)out_size;
    const float* ptl = (const float*)d_in[0];
    float* out = (float*)d_out;
    dim3 grid(BLKS_PER_MAT, NMAT);   // (9, 16) = 144 blocks, 128 threads
    eval_eig_kernel<<<grid, NTHREADS>>>(ptl, out);
}